// round 6
// baseline (speedup 1.0000x reference)
#include <cuda_runtime.h>
#include <cuda_fp16.h>
#include <cstdint>
#include <cfloat>

#define N_ROWS 65536
#define DIM    1024
#define KCB    8192

#define TAU      0.06f     // fp16 margin threshold (~12 sigma)
#define TAU2     2.0e-3f   // refine candidate window (fp32-noise scale)
#define WL_CAP   8192
#define CAND_CAP 32

// ---- HMMA GEMM tiling ----
#define BM 128
#define BN 128
#define KC 64
#define N_TILES (KCB / BN)                       // 64
#define CHUNKS_PER_TILE (DIM / KC)               // 16
#define TOTAL_CHUNKS (N_TILES * CHUNKS_PER_TILE) // 1024
#define GEMM_THREADS 256

// ---- dynamic SMEM layout (bytes) ----
#define TILE_BYTES   16384            // 128 rows x 64 fp16 (128B rows, SW128)
#define STAGE_BYTES  32768            // A tile + B tile
#define SM_A_OFF     0
#define SM_B_OFF     16384
#define NSTAGES      3
#define SM_EPI       (NSTAGES * STAGE_BYTES)     // 98304
#define EPI_B        0                           // float[128*4]
#define EPI_S        2048
#define EPI_I        4096
#define GEMM_SMEM    (SM_EPI + 6144)             // 104448

// ---- scratch (__device__ globals; allocation-free rule) ----
__device__ __half g_zh[(size_t)N_ROWS * DIM];    // 128 MB
__device__ __half g_ch[(size_t)KCB * DIM];       // 16 MB
__device__ float  g_cbT[(size_t)KCB * DIM];      // 32 MB fp32 (refine + gather)
__device__ int    g_argmin[N_ROWS];
__device__ int    g_wl[WL_CAP];
__device__ int    g_wl_count;

// ============================ helpers ============================
__device__ __forceinline__ uint32_t smem_to_u32(const void* p) {
    uint32_t a;
    asm("{ .reg .u64 t; cvta.to.shared.u64 t, %1; cvt.u32.u64 %0, t; }" : "=r"(a) : "l"(p));
    return a;
}
#define SWZ128(o) ((o) ^ (((o) >> 3) & 0x70))

#define CP_ASYNC16(sm, g) \
    asm volatile("cp.async.cg.shared.global [%0], [%1], 16;" :: "r"(sm), "l"(g) : "memory")
#define CP_COMMIT()  asm volatile("cp.async.commit_group;" ::: "memory")
#define CP_WAIT2()   asm volatile("cp.async.wait_group 2;" ::: "memory")
#define CP_WAIT1()   asm volatile("cp.async.wait_group 1;" ::: "memory")
#define CP_WAIT0()   asm volatile("cp.async.wait_group 0;" ::: "memory")

#define LDMATRIX_X4(r0, r1, r2, r3, a) \
    asm volatile("ldmatrix.sync.aligned.m8n8.x4.shared.b16 {%0,%1,%2,%3}, [%4];" \
                 : "=r"(r0), "=r"(r1), "=r"(r2), "=r"(r3) : "r"(a))

#define MMA_F16(c0, c1, c2, c3, a0, a1, a2, a3, b0, b1) \
    asm volatile("mma.sync.aligned.m16n8k16.row.col.f32.f16.f16.f32 " \
                 "{%0,%1,%2,%3}, {%4,%5,%6,%7}, {%8,%9}, {%0,%1,%2,%3};" \
                 : "+f"(c0), "+f"(c1), "+f"(c2), "+f"(c3) \
                 : "r"(a0), "r"(a1), "r"(a2), "r"(a3), "r"(b0), "r"(b1))

// ---------------------------------------------------------------------------
// Prep 1: transpose codebook -> g_cbT fp32 + g_ch fp16; reset worklist.
// ---------------------------------------------------------------------------
__global__ void vq_prep_cb(const float* __restrict__ cb) {
    if (blockIdx.x == 0 && blockIdx.y == 0 && threadIdx.x == 0 && threadIdx.y == 0)
        g_wl_count = 0;
    __shared__ float tile[32][33];
    const int kBase = blockIdx.x * 32;
    const int dBase = blockIdx.y * 32;
    const int tx = threadIdx.x, ty = threadIdx.y;
#pragma unroll
    for (int i = 0; i < 4; i++)
        tile[ty + i * 8][tx] = cb[(size_t)(dBase + ty + i * 8) * KCB + (kBase + tx)];
    __syncthreads();
#pragma unroll
    for (int i = 0; i < 4; i++) {
        const float v = tile[tx][ty + i * 8];
        const size_t o = (size_t)(kBase + ty + i * 8) * DIM + (dBase + tx);
        g_cbT[o] = v;
        g_ch[o] = __float2half(v);
    }
}

// ---------------------------------------------------------------------------
// Prep 2: z -> fp16.
// ---------------------------------------------------------------------------
__global__ void vq_prep_z(const float* __restrict__ z) {
    const size_t total4 = (size_t)N_ROWS * DIM / 4;
    const size_t stride = (size_t)gridDim.x * blockDim.x;
    const float4* z4 = (const float4*)z;
    __half2* h2 = (__half2*)g_zh;
    for (size_t t = (size_t)blockIdx.x * blockDim.x + threadIdx.x; t < total4; t += stride) {
        const float4 v = z4[t];
        h2[t * 2 + 0] = __floats2half2_rn(v.x, v.y);
        h2[t * 2 + 1] = __floats2half2_rn(v.z, v.w);
    }
}

// ---------------------------------------------------------------------------
// Main: single-pass fp16 HMMA GEMM + fused argmin with runner-up margin.
// ---------------------------------------------------------------------------
__global__ __launch_bounds__(GEMM_THREADS)
void vq_hmma_kernel() {
    extern __shared__ char smem[];
    const uint32_t sb = smem_to_u32(smem);
    const int tid  = threadIdx.x;
    const int wid  = tid >> 5;
    const int lane = tid & 31;
    const int wm   = wid >> 2;            // 0..1 (M group of 64)
    const int wn   = wid & 3;             // 0..3 (N group of 32)
    const int t4   = lane >> 2;           // 0..7
    const int tq   = lane & 3;            // 0..3
    const int rowBase = blockIdx.x * BM;

    // per-chunk loader: 8 x 16B cp.async per thread
    auto load_chunk = [&](int C) {
        const int nt = C >> 4, c = C & 15;
        const uint32_t stage = sb + (C % NSTAGES) * STAGE_BYTES;
        const int koff = c * KC;
        const int ntBase = nt * BN;
#pragma unroll
        for (int i = 0; i < 4; i++) {
            const int sg = tid + i * 256;        // 0..1023
            const int row = sg >> 3, sc = sg & 7;
            const uint32_t so = SWZ128(row * 128 + sc * 16);
            const size_t ga = (size_t)(rowBase + row) * DIM + koff + sc * 8;
            const size_t gb = (size_t)(ntBase + row) * DIM + koff + sc * 8;
            CP_ASYNC16(stage + SM_A_OFF + so, g_zh + ga);
            CP_ASYNC16(stage + SM_B_OFF + so, g_ch + gb);
        }
        CP_COMMIT();
    };

    float acc[4][4][4];
    float rBest = FLT_MAX, rSec = FLT_MAX;
    int   rIdx = 0x7FFFFFFF;

    // ldmatrix lane-address components
    const int am  = lane >> 3;            // matrix id 0..3
    const int ar  = lane & 7;
    const int aRow = ((am & 1) << 3) + ar;
    const int aColB = (am >> 1) << 4;
    const int bRow = ((am >> 1) << 3) + ar;
    const int bColB = (am & 1) << 4;

    load_chunk(0);
    load_chunk(1);
    load_chunk(2);

    for (int C = 0; C < TOTAL_CHUNKS; C++) {
        const int nt = C >> 4, c = C & 15;

        const int remaining = TOTAL_CHUNKS - 1 - C;
        if (remaining >= 2)      { CP_WAIT2(); }
        else if (remaining == 1) { CP_WAIT1(); }
        else                     { CP_WAIT0(); }
        __syncthreads();

        if (c == 0) {
#pragma unroll
            for (int mi = 0; mi < 4; mi++)
#pragma unroll
                for (int ni = 0; ni < 4; ni++)
#pragma unroll
                    for (int r = 0; r < 4; r++) acc[mi][ni][r] = 0.0f;
        }

        const uint32_t stage = sb + (C % NSTAGES) * STAGE_BYTES;
        const uint32_t aB = stage + SM_A_OFF, bB = stage + SM_B_OFF;

#pragma unroll
        for (int ks = 0; ks < 4; ks++) {
            const int kb = ks * 32;       // 16 fp16 = 32 bytes per k-step
            uint32_t af[16], bf[16];

#pragma unroll
            for (int mi = 0; mi < 4; mi++) {
                const int row = wm * 64 + mi * 16 + aRow;
                const uint32_t ad = aB + SWZ128(row * 128 + kb + aColB);
                LDMATRIX_X4(af[mi*4+0], af[mi*4+1], af[mi*4+2], af[mi*4+3], ad);
            }
#pragma unroll
            for (int np = 0; np < 2; np++) {
                const int nrow = wn * 32 + np * 16 + bRow;
                const uint32_t bd = bB + SWZ128(nrow * 128 + kb + bColB);
                LDMATRIX_X4(bf[np*8+0], bf[np*8+1], bf[np*8+4], bf[np*8+5], bd);
            }

#pragma unroll
            for (int mi = 0; mi < 4; mi++)
#pragma unroll
                for (int ni = 0; ni < 4; ni++)
                    MMA_F16(acc[mi][ni][0], acc[mi][ni][1], acc[mi][ni][2], acc[mi][ni][3],
                            af[mi*4+0], af[mi*4+1], af[mi*4+2], af[mi*4+3],
                            bf[ni*4+0], bf[ni*4+1]);
        }
        __syncthreads();

        if (C + 3 < TOTAL_CHUNKS) load_chunk(C + 3);

        // ---- n-tile epilogue ----
        if (c == 15) {
            float* eB = (float*)(smem + SM_EPI + EPI_B);
            float* eS = (float*)(smem + SM_EPI + EPI_S);
            int*   eI = (int*)(smem + SM_EPI + EPI_I);
            const int colBase = nt * BN + wn * 32 + tq * 2;

#pragma unroll
            for (int mi = 0; mi < 4; mi++) {
#pragma unroll
                for (int half = 0; half < 2; half++) {
                    const int row = wm * 64 + mi * 16 + half * 8 + t4;
                    float b = FLT_MAX, sv = FLT_MAX;
                    int   bi = 0x7FFFFFFF;
#pragma unroll
                    for (int ni = 0; ni < 4; ni++) {
#pragma unroll
                        for (int cc = 0; cc < 2; cc++) {
                            const float v = acc[mi][ni][half * 2 + cc];
                            const int col = colBase + ni * 8 + cc;
                            if (v < b) { sv = b; b = v; bi = col; }
                            else       { sv = fminf(sv, v); }
                        }
                    }
#pragma unroll
                    for (int off = 1; off <= 2; off <<= 1) {
                        const float ob = __shfl_xor_sync(0xFFFFFFFFu, b, off);
                        const float os = __shfl_xor_sync(0xFFFFFFFFu, sv, off);
                        const int   oi = __shfl_xor_sync(0xFFFFFFFFu, bi, off);
                        if (ob < b || (ob == b && oi < bi)) {
                            sv = fminf(b, os); b = ob; bi = oi;
                        } else {
                            sv = fminf(sv, ob);
                        }
                    }
                    if (tq == 0) {
                        eB[row * 4 + wn] = b;
                        eS[row * 4 + wn] = sv;
                        eI[row * 4 + wn] = bi;
                    }
                }
            }
            __syncthreads();
            if (tid < BM) {
#pragma unroll
                for (int w = 0; w < 4; w++) {
                    const float b = eB[tid * 4 + w];
                    const float sv = eS[tid * 4 + w];
                    const int   bi = eI[tid * 4 + w];
                    if (b < rBest || (b == rBest && bi < rIdx)) {
                        rSec = fminf(rBest, sv);
                        rBest = b; rIdx = bi;
                    } else {
                        rSec = fminf(rSec, fminf(b, sv));
                    }
                }
            }
            __syncthreads();
        }
    }

    if (tid < BM) {
        const int row = rowBase + tid;
        g_argmin[row] = rIdx;
        if (rSec - rBest < TAU) {
            const int p = atomicAdd(&g_wl_count, 1);
            if (p < WL_CAP) g_wl[p] = row;
        }
    }
}

// ---------------------------------------------------------------------------
// Refine: 4 rows/CTA, warp = (row, codebook-half). z row in registers.
// Online candidate collection vs running min; fp64 exact rescore of survivors.
// ---------------------------------------------------------------------------
#define RB 4
__global__ __launch_bounds__(256)
void vq_refine_kernel(const float* __restrict__ A) {
    __shared__ float  zs[RB][DIM];                 // 16 KB
    __shared__ int    rws[RB];
    __shared__ float  hmin[RB][2];
    __shared__ int    hcnt[RB][2];
    __shared__ int    hidx[RB][2][CAND_CAP];
    __shared__ float  hval[RB][2][CAND_CAP];

    const int tid  = threadIdx.x;
    const int lane = tid & 31;
    const int wrp  = tid >> 5;            // 0..7
    const int r    = wrp >> 1;            // 0..3
    const int h    = wrp & 1;             // 0..1
    const int cnt  = min(g_wl_count, WL_CAP);
    const int nB   = (cnt + RB - 1) / RB;

    for (int b = blockIdx.x; b < nB; b += gridDim.x) {
        if (tid < RB) rws[tid] = (b * RB + tid < cnt) ? g_wl[b * RB + tid] : -1;
        if (tid < RB * 2) hcnt[tid >> 1][tid & 1] = 0;
        __syncthreads();

        for (int i = tid; i < RB * DIM; i += 256) {
            const int rr = i >> 10, dd = i & 1023;
            zs[rr][dd] = (rws[rr] >= 0) ? A[(size_t)rws[rr] * DIM + dd] : 0.0f;
        }
        __syncthreads();

        const bool active = rws[r] >= 0;

        // z row in registers: lane owns float4 chunks lane + 32q
        float4 zr[8];
#pragma unroll
        for (int q = 0; q < 8; q++)
            zr[q] = ((const float4*)zs[r])[lane + 32 * q];

        float wmin = FLT_MAX;
        const int kBeg = h * (KCB / 2), kEnd = kBeg + KCB / 2;
        for (int k = kBeg; k < kEnd; k++) {
            const float4* cw = (const float4*)(g_cbT + (size_t)k * DIM);
            float s = 0.0f;
#pragma unroll
            for (int q = 0; q < 8; q++) {
                const float4 c = cw[lane + 32 * q];
                s = fmaf(c.x, zr[q].x, s);
                s = fmaf(c.y, zr[q].y, s);
                s = fmaf(c.z, zr[q].z, s);
                s = fmaf(c.w, zr[q].w, s);
            }
#pragma unroll
            for (int off = 16; off > 0; off >>= 1)
                s += __shfl_down_sync(0xFFFFFFFFu, s, off);
            if (lane == 0 && active) {
                if (s < wmin + TAU2) {
                    const int p = hcnt[r][h];
                    if (p < CAND_CAP) {
                        hidx[r][h][p] = k;
                        hval[r][h][p] = s;
                        hcnt[r][h] = p + 1;
                    }
                    if (s < wmin) wmin = s;
                }
            }
        }
        if (lane == 0) hmin[r][h] = wmin;
        __syncthreads();

        // warp (r, 0) finalizes row r
        if (h == 0 && active) {
            const float bmin = fminf(hmin[r][0], hmin[r][1]);
            double bestV = 1e300;
            int    bestI = 0x7FFFFFFF;
#pragma unroll
            for (int hh = 0; hh < 2; hh++) {
                const int nc = min(hcnt[r][hh], CAND_CAP);
                for (int ci = 0; ci < nc; ci++) {
                    // broadcast candidate to whole warp
                    const float v = hval[r][hh][ci];
                    if (v >= bmin + TAU2) continue;
                    const int k = hidx[r][hh][ci];
                    const float* cw = g_cbT + (size_t)k * DIM;
                    double sd = 0.0;
#pragma unroll
                    for (int q = 0; q < 8; q++) {
#pragma unroll
                        for (int e = 0; e < 4; e++) {
                            const int d = (lane + 32 * q) * 4 + e;
                            sd += (double)cw[d] * (double)zs[r][d];
                        }
                    }
#pragma unroll
                    for (int off = 16; off > 0; off >>= 1)
                        sd += __shfl_down_sync(0xFFFFFFFFu, sd, off);
                    if (lane == 0) {
                        if (sd < bestV || (sd == bestV && k < bestI)) {
                            bestV = sd; bestI = k;
                        }
                    }
                }
            }
            if (lane == 0) g_argmin[rws[r]] = bestI;
        }
        __syncthreads();
    }
}

// ---------------------------------------------------------------------------
// Gather: out[n][:] = g_cbT[argmin[n]][:]
// ---------------------------------------------------------------------------
__global__ void vq_gather_kernel(float* __restrict__ out) {
    const int n = blockIdx.x;
    const int idx = g_argmin[n];
    const float4* src = (const float4*)(g_cbT + (size_t)idx * DIM);
    float4* dst = (float4*)(out + (size_t)n * DIM);
    dst[threadIdx.x] = src[threadIdx.x];
}

// ---------------------------------------------------------------------------
extern "C" void kernel_launch(void* const* d_in, const int* in_sizes, int n_in,
                              void* d_out, int out_size) {
    const float* z  = (const float*)d_in[0];
    const float* cb = (const float*)d_in[1];
    float* out = (float*)d_out;

    cudaFuncSetAttribute(vq_hmma_kernel, cudaFuncAttributeMaxDynamicSharedMemorySize, GEMM_SMEM);

    dim3 tgrid(KCB / 32, DIM / 32);
    dim3 tblk(32, 8);
    vq_prep_cb<<<tgrid, tblk>>>(cb);
    vq_prep_z<<<8192, 256>>>(z);

    vq_hmma_kernel<<<N_ROWS / BM, GEMM_THREADS, GEMM_SMEM>>>();

    vq_refine_kernel<<<592, 256>>>(z);
    vq_gather_kernel<<<N_ROWS, 256>>>(out);
}